// round 1
// baseline (speedup 1.0000x reference)
#include <cuda_runtime.h>

// ---------------- constants ----------------
#define E_    192
#define DI_   384
#define NS_   16
#define NR_   12
#define L_    401
#define BATCH_ 32
#define NTOK_ (BATCH_*L_)     // 12832
#define XP_   48              // padded xdb row stride (44 used)
#define EPS_  1e-5f

// ---------------- scratch (static device globals; no allocation) ----------------
__device__ float g_x  [NTOK_*E_];        // hidden
__device__ float g_res[NTOK_*E_];        // residual
__device__ float g_hn [NTOK_*E_];        // rmsnorm output
__device__ float g_xz [NTOK_*2*DI_];     // in_proj out (xm | z)
__device__ float g_xc [NTOK_*DI_];       // conv+silu out
__device__ float g_xdb[NTOK_*XP_];       // x_proj out (dt_r | B | C), padded
__device__ float g_dt [NTOK_*DI_];       // softplus(dt)
__device__ float g_y  [NTOK_*DI_];       // scan output (gated)

// ---------------- patch embed + pos + cnn conv + cls ----------------
__global__ void k_embed(const float* __restrict__ imgs, const float* __restrict__ pw,
                        const float* __restrict__ pb,   const float* __restrict__ cls,
                        const float* __restrict__ pos,  const float* __restrict__ cw,
                        const float* __restrict__ cb)
{
    int idx = blockIdx.x*blockDim.x + threadIdx.x;
    if (idx >= NTOK_*E_) return;
    int e = idx % E_;
    int t = idx / E_;
    int l = t % L_;
    int b = t / L_;
    float v;
    if (l == L_-1) {
        v = cls[e] + pos[(L_-1)*E_ + e];
    } else {
        float acc = cb[e];
        const float* w4 = pw + e*4;
#pragma unroll
        for (int k = 0; k < 3; k++) {
            int ls = l - 1 + k;
            if (ls >= 0 && ls < 400) {
                const float* im = imgs + b*1600 + ls*4;
                float pe = im[0]*w4[0] + im[1]*w4[1] + im[2]*w4[2] + im[3]*w4[3]
                         + pb[e] + pos[ls*E_ + e];
                acc = fmaf(pe, cw[e*3 + k], acc);
            }
        }
        v = acc;
    }
    g_x[t*E_ + e] = v;
}

// ---------------- residual accumulate + rmsnorm ----------------
__global__ void k_resnorm(const float* __restrict__ norm_w, int first)
{
    int t = blockIdx.x;
    int e = threadIdx.x;     // 192 threads
    float r = g_x[t*E_ + e];
    if (!first) r += g_res[t*E_ + e];
    g_res[t*E_ + e] = r;
    float s = r*r;
#pragma unroll
    for (int o = 16; o > 0; o >>= 1) s += __shfl_down_sync(0xffffffffu, s, o);
    __shared__ float ws[6];
    __shared__ float s_inv;
    int w = e >> 5, lane = e & 31;
    if (lane == 0) ws[w] = s;
    __syncthreads();
    if (e == 0) {
        float tot = ws[0]+ws[1]+ws[2]+ws[3]+ws[4]+ws[5];
        s_inv = rsqrtf(tot * (1.0f/E_) + EPS_);
    }
    __syncthreads();
    g_hn[t*E_ + e] = r * s_inv * norm_w[e];
}

// ---------------- generic SGEMM: C[M,Nn] = A[M,K] * B[Nn,K]^T ----------------
#define BM_ 128
#define BN_ 64
#define BK_ 16
__global__ __launch_bounds__(128)
void sgemm(const float* __restrict__ A, const float* __restrict__ B,
           float* __restrict__ C, int M, int Nn, int K, int ldc)
{
    __shared__ float As[BK_][BM_];
    __shared__ float Bs[BK_][BN_];
    int tid = threadIdx.x;
    int tn = tid & 7;       // 0..7  (TN=8 columns of 8)
    int tm = tid >> 3;      // 0..15 (TM=8 rows of 8)
    int m0 = blockIdx.y * BM_;
    int n0 = blockIdx.x * BN_;
    float acc[8][8];
#pragma unroll
    for (int i = 0; i < 8; i++)
#pragma unroll
        for (int j = 0; j < 8; j++) acc[i][j] = 0.f;

    for (int k0 = 0; k0 < K; k0 += BK_) {
#pragma unroll
        for (int j = 0; j < 4; j++) {          // A tile: 128x16 = 512 float4
            int idx = tid + j*128;
            int row = idx >> 2, kq = idx & 3;
            float4 v = make_float4(0.f,0.f,0.f,0.f);
            if (m0 + row < M) v = *(const float4*)(A + (long)(m0+row)*K + k0 + kq*4);
            As[kq*4+0][row] = v.x; As[kq*4+1][row] = v.y;
            As[kq*4+2][row] = v.z; As[kq*4+3][row] = v.w;
        }
#pragma unroll
        for (int j = 0; j < 2; j++) {          // B tile: 64x16 = 256 float4
            int idx = tid + j*128;
            int row = idx >> 2, kq = idx & 3;
            float4 v = make_float4(0.f,0.f,0.f,0.f);
            if (n0 + row < Nn) v = *(const float4*)(B + (long)(n0+row)*K + k0 + kq*4);
            Bs[kq*4+0][row] = v.x; Bs[kq*4+1][row] = v.y;
            Bs[kq*4+2][row] = v.z; Bs[kq*4+3][row] = v.w;
        }
        __syncthreads();
#pragma unroll
        for (int kk = 0; kk < BK_; kk++) {
            float4 a0 = *(const float4*)&As[kk][tm*8];
            float4 a1 = *(const float4*)&As[kk][tm*8+4];
            float4 b0 = *(const float4*)&Bs[kk][tn*8];
            float4 b1 = *(const float4*)&Bs[kk][tn*8+4];
            float ra[8] = {a0.x,a0.y,a0.z,a0.w,a1.x,a1.y,a1.z,a1.w};
            float rb[8] = {b0.x,b0.y,b0.z,b0.w,b1.x,b1.y,b1.z,b1.w};
#pragma unroll
            for (int i = 0; i < 8; i++)
#pragma unroll
                for (int j = 0; j < 8; j++)
                    acc[i][j] = fmaf(ra[i], rb[j], acc[i][j]);
        }
        __syncthreads();
    }
#pragma unroll
    for (int i = 0; i < 8; i++) {
        int row = m0 + tm*8 + i;
        if (row < M) {
#pragma unroll
            for (int j = 0; j < 8; j++) {
                int col = n0 + tn*8 + j;
                if (col < Nn) C[(long)row*ldc + col] = acc[i][j];
            }
        }
    }
}

// ---------------- causal depthwise conv(4) + silu ----------------
__global__ void k_conv(const float* __restrict__ cw, const float* __restrict__ cb)
{
    int idx = blockIdx.x*blockDim.x + threadIdx.x;
    if (idx >= NTOK_*DI_) return;
    int d = idx % DI_;
    int t = idx / DI_;
    int l = t % L_;
    float acc = cb[d];
    const float* w = cw + d*4;
#pragma unroll
    for (int k = 0; k < 4; k++) {
        int ls = l - 3 + k;
        if (ls >= 0) acc = fmaf(g_xz[(long)(t + ls - l)*(2*DI_) + d], w[k], acc);
    }
    float sg = 1.f / (1.f + expf(-acc));
    g_xc[t*DI_ + d] = acc * sg;
}

// ---------------- dt = softplus(xdb[:, :12] @ dtw^T + dtb) ----------------
__global__ void k_dt(const float* __restrict__ dtw, const float* __restrict__ dtb)
{
    int idx = blockIdx.x*blockDim.x + threadIdx.x;
    if (idx >= NTOK_*DI_) return;
    int d = idx % DI_;
    int t = idx / DI_;
    float acc = dtb[d];
    const float* w = dtw + d*NR_;
    const float* x = g_xdb + (long)t*XP_;
#pragma unroll
    for (int r = 0; r < NR_; r++) acc = fmaf(x[r], w[r], acc);
    float sp = fmaxf(acc, 0.f) + log1pf(expf(-fabsf(acc)));
    g_dt[t*DI_ + d] = sp;
}

// ---------------- selective scan (serial over L, parallel over b,d) ----------------
// grid (4, 32), block 96 : one thread per (b, d), 16 states in registers
__global__ __launch_bounds__(96)
void k_scan(const float* __restrict__ A_log, const float* __restrict__ Dsk)
{
    int d = blockIdx.x * 96 + threadIdx.x;   // 0..383
    int b = blockIdx.y;
    float a[NS_];
#pragma unroll
    for (int n = 0; n < NS_; n++) a[n] = -expf(A_log[d*NS_ + n]);
    float dsk = Dsk[d];
    float h[NS_];
#pragma unroll
    for (int n = 0; n < NS_; n++) h[n] = 0.f;

    for (int l = 0; l < L_; l++) {
        int t = b*L_ + l;
        const float4* q = (const float4*)(g_xdb + (long)t*XP_);
        float4 B0 = q[3], B1 = q[4], B2 = q[5], B3 = q[6];
        float4 C0 = q[7], C1 = q[8], C2 = q[9], C3 = q[10];
        float Bv[NS_] = {B0.x,B0.y,B0.z,B0.w, B1.x,B1.y,B1.z,B1.w,
                         B2.x,B2.y,B2.z,B2.w, B3.x,B3.y,B3.z,B3.w};
        float Cv[NS_] = {C0.x,C0.y,C0.z,C0.w, C1.x,C1.y,C1.z,C1.w,
                         C2.x,C2.y,C2.z,C2.w, C3.x,C3.y,C3.z,C3.w};
        float dt = g_dt[(long)t*DI_ + d];
        float u  = g_xc[(long)t*DI_ + d];
        float du = dt * u;
        float yv = 0.f;
#pragma unroll
        for (int n = 0; n < NS_; n++) {
            float dA = expf(dt * a[n]);
            h[n] = fmaf(h[n], dA, du * Bv[n]);
            yv = fmaf(h[n], Cv[n], yv);
        }
        float z = g_xz[(long)t*(2*DI_) + DI_ + d];
        float sg = z / (1.f + expf(-z));
        g_y[(long)t*DI_ + d] = (yv + u*dsk) * sg;
    }
}

// ---------------- layer-3 out_proj: only last tokens matter ----------------
__global__ void k_outlast(const float* __restrict__ ow)
{
    int b = blockIdx.x;
    int e = threadIdx.x;         // 192
    __shared__ float ys[DI_];
    int t = b*L_ + (L_-1);
    for (int i = e; i < DI_; i += E_) ys[i] = g_y[(long)t*DI_ + i];
    __syncthreads();
    float acc = 0.f;
    const float* w = ow + e*DI_;
#pragma unroll 4
    for (int d2 = 0; d2 < DI_; d2++) acc = fmaf(ys[d2], w[d2], acc);
    g_x[t*E_ + e] = acc;
}

// ---------------- final rmsnorm (last token) + classifier head ----------------
__global__ void k_final(const float* __restrict__ nfw, const float* __restrict__ hw,
                        const float* __restrict__ hb, float* __restrict__ out)
{
    int b = blockIdx.x;
    int e = threadIdx.x;         // 192
    int t = b*L_ + (L_-1);
    float r = g_x[t*E_ + e] + g_res[t*E_ + e];
    float s = r*r;
#pragma unroll
    for (int o = 16; o > 0; o >>= 1) s += __shfl_down_sync(0xffffffffu, s, o);
    __shared__ float ws[6];
    __shared__ float s_inv;
    __shared__ float vs[E_];
    int w = e >> 5, lane = e & 31;
    if (lane == 0) ws[w] = s;
    __syncthreads();
    if (e == 0) {
        float tot = ws[0]+ws[1]+ws[2]+ws[3]+ws[4]+ws[5];
        s_inv = rsqrtf(tot * (1.0f/E_) + EPS_);
    }
    __syncthreads();
    vs[e] = r * s_inv * nfw[e];
    __syncthreads();
    if (e < 20) {
        float acc = hb[e];
        const float* wr = hw + e*E_;
#pragma unroll 4
        for (int j = 0; j < E_; j++) acc = fmaf(vs[j], wr[j], acc);
        out[b*20 + e] = acc;
    }
}

// ---------------- launch ----------------
extern "C" void kernel_launch(void* const* d_in, const int* in_sizes, int n_in,
                              void* d_out, int out_size)
{
    const float* imgs      = (const float*)d_in[0];
    const float* patch_w   = (const float*)d_in[1];
    const float* patch_b   = (const float*)d_in[2];
    const float* cls_token = (const float*)d_in[3];
    const float* pos_embed = (const float*)d_in[4];
    const float* cnn_w     = (const float*)d_in[5];
    const float* cnn_b     = (const float*)d_in[6];
    const float* norm_w    = (const float*)d_in[7];
    const float* in_proj_w = (const float*)d_in[8];
    const float* conv_w    = (const float*)d_in[9];
    const float* conv_b    = (const float*)d_in[10];
    const float* x_proj_w  = (const float*)d_in[11];
    const float* dt_proj_w = (const float*)d_in[12];
    const float* dt_proj_b = (const float*)d_in[13];
    const float* A_log     = (const float*)d_in[14];
    const float* D_skip    = (const float*)d_in[15];
    const float* out_proj_w= (const float*)d_in[16];
    const float* norm_f_w  = (const float*)d_in[17];
    const float* head_w    = (const float*)d_in[18];
    const float* head_b    = (const float*)d_in[19];
    float* out = (float*)d_out;

    float *p_hn, *p_xz, *p_xc, *p_xdb, *p_y, *p_x;
    cudaGetSymbolAddress((void**)&p_hn,  g_hn);
    cudaGetSymbolAddress((void**)&p_xz,  g_xz);
    cudaGetSymbolAddress((void**)&p_xc,  g_xc);
    cudaGetSymbolAddress((void**)&p_xdb, g_xdb);
    cudaGetSymbolAddress((void**)&p_y,   g_y);
    cudaGetSymbolAddress((void**)&p_x,   g_x);

    k_embed<<<(NTOK_*E_ + 255)/256, 256>>>(imgs, patch_w, patch_b, cls_token,
                                           pos_embed, cnn_w, cnn_b);

    const int MGRID = (NTOK_ + BM_ - 1) / BM_;   // 101
    dim3 gIn (2*DI_/BN_, MGRID);   // (12,101)
    dim3 gXp (1,         MGRID);   // (1,101)
    dim3 gOut(E_/BN_,    MGRID);   // (3,101)
    int ew_blocks = (NTOK_*DI_ + 255)/256;

    for (int i = 0; i < 4; i++) {
        k_resnorm<<<NTOK_, E_>>>(norm_w + i*E_, i == 0);
        sgemm<<<gIn, 128>>>(p_hn, in_proj_w + (long)i*2*DI_*E_, p_xz,
                            NTOK_, 2*DI_, E_, 2*DI_);
        k_conv<<<ew_blocks, 256>>>(conv_w + (long)i*DI_*4, conv_b + i*DI_);
        sgemm<<<gXp, 128>>>(p_xc, x_proj_w + (long)i*(NR_+2*NS_)*DI_, p_xdb,
                            NTOK_, NR_+2*NS_, DI_, XP_);
        k_dt<<<ew_blocks, 256>>>(dt_proj_w + (long)i*DI_*NR_, dt_proj_b + i*DI_);
        k_scan<<<dim3(4, BATCH_), 96>>>(A_log + (long)i*DI_*NS_, D_skip + i*DI_);
        if (i < 3) {
            sgemm<<<gOut, 128>>>(p_y, out_proj_w + (long)i*E_*DI_, p_x,
                                 NTOK_, E_, DI_, E_);
        } else {
            k_outlast<<<BATCH_, E_>>>(out_proj_w + (long)i*E_*DI_);
        }
    }
    k_final<<<BATCH_, E_>>>(norm_f_w, head_w, head_b, out);
}

// round 3
// speedup vs baseline: 1.0423x; 1.0423x over previous
#include <cuda_runtime.h>

// ---------------- constants ----------------
#define E_    192
#define DI_   384
#define NS_   16
#define NR_   12
#define L_    401
#define BATCH_ 32
#define NTOK_ (BATCH_*L_)     // 12832
#define XP_   48              // padded xdb row stride (44 used)
#define EPS_  1e-5f

// ---------------- scratch (static device globals; no allocation) ----------------
__device__ float g_x  [NTOK_*E_];        // hidden
__device__ float g_res[NTOK_*E_];        // residual
__device__ float g_hn [NTOK_*E_];        // rmsnorm output
__device__ float g_xz [NTOK_*2*DI_];     // in_proj out (xm | z)
__device__ float g_xc [NTOK_*DI_];       // conv+silu out
__device__ float g_xdb[NTOK_*XP_];       // x_proj out (dt_r | B | C), padded
__device__ float g_dt [NTOK_*DI_];       // softplus(dt)
__device__ float g_y  [NTOK_*DI_];       // scan output (gated)

// ---------------- packed f32x2 helpers (sm_103a FFMA2) ----------------
#define FMA_F32X2(d, a, b, c) \
    asm("fma.rn.f32x2 %0, %1, %2, %3;" : "=l"(d) : "l"(a), "l"(b), "l"(c))
#define PACK_DUP_F32(d, x) \
    asm("mov.b64 %0, {%1, %1};" : "=l"(d) : "f"(x))

// ---------------- patch embed + pos + cnn conv + cls ----------------
__global__ void k_embed(const float* __restrict__ imgs, const float* __restrict__ pw,
                        const float* __restrict__ pb,   const float* __restrict__ cls,
                        const float* __restrict__ pos,  const float* __restrict__ cw,
                        const float* __restrict__ cb)
{
    int idx = blockIdx.x*blockDim.x + threadIdx.x;
    if (idx >= NTOK_*E_) return;
    int e = idx % E_;
    int t = idx / E_;
    int l = t % L_;
    int b = t / L_;
    float v;
    if (l == L_-1) {
        v = cls[e] + pos[(L_-1)*E_ + e];
    } else {
        float acc = cb[e];
        const float* w4 = pw + e*4;
#pragma unroll
        for (int k = 0; k < 3; k++) {
            int ls = l - 1 + k;
            if (ls >= 0 && ls < 400) {
                const float* im = imgs + b*1600 + ls*4;
                float pe = im[0]*w4[0] + im[1]*w4[1] + im[2]*w4[2] + im[3]*w4[3]
                         + pb[e] + pos[ls*E_ + e];
                acc = fmaf(pe, cw[e*3 + k], acc);
            }
        }
        v = acc;
    }
    g_x[t*E_ + e] = v;
}

// ---------------- residual accumulate + rmsnorm ----------------
__global__ void k_resnorm(const float* __restrict__ norm_w, int first)
{
    int t = blockIdx.x;
    int e = threadIdx.x;     // 192 threads
    float r = g_x[t*E_ + e];
    if (!first) r += g_res[t*E_ + e];
    g_res[t*E_ + e] = r;
    float s = r*r;
#pragma unroll
    for (int o = 16; o > 0; o >>= 1) s += __shfl_down_sync(0xffffffffu, s, o);
    __shared__ float ws[6];
    __shared__ float s_inv;
    int w = e >> 5, lane = e & 31;
    if (lane == 0) ws[w] = s;
    __syncthreads();
    if (e == 0) {
        float tot = ws[0]+ws[1]+ws[2]+ws[3]+ws[4]+ws[5];
        s_inv = rsqrtf(tot * (1.0f/E_) + EPS_);
    }
    __syncthreads();
    g_hn[t*E_ + e] = r * s_inv * norm_w[e];
}

// =========================================================================
// Double-buffered f32x2 SGEMM: C[M,Nn] = A[M,K] * B[Nn,K]^T
// 128 x (16*TN) tile, BK=16, 256 threads, 8 x TN microtile per thread.
// TN=8 -> 128-wide tiles (in_proj), TN=4 -> 64-wide tiles (out_proj).
// =========================================================================
#define DBK_ 16
template<int TN>
__global__ __launch_bounds__(256, 2)
void sgemm_db(const float* __restrict__ A, const float* __restrict__ Bm,
              float* __restrict__ C, int M, int Nn, int K, int ldc)
{
    constexpr int TBN = 16*TN;
    constexpr int NBLOAD = (TBN*DBK_/4)/256;   // float4 B loads per thread (2 or 1)
    __shared__ float As[2][DBK_][128];
    __shared__ float Bs[2][DBK_][TBN];

    int tid = threadIdx.x;
    int tn = tid & 15;          // 0..15
    int tm = tid >> 4;          // 0..15
    int m0 = blockIdx.y * 128;
    int n0 = blockIdx.x * TBN;

    int lrow = tid >> 2;        // 0..63
    int lkq  = tid & 3;         // 0..3

    float4 rega[2];
    float4 regb[NBLOAD];

    unsigned long long acc[8][TN/2];
#pragma unroll
    for (int i = 0; i < 8; i++)
#pragma unroll
        for (int j = 0; j < TN/2; j++) acc[i][j] = 0ull;

    // ---- macros for load / store-to-smem ----
#define LDG_TILE(k0)                                                          \
    {                                                                         \
        _Pragma("unroll")                                                     \
        for (int i = 0; i < 2; i++) {                                         \
            int r = lrow + i*64;                                              \
            rega[i] = (m0 + r < M)                                            \
                ? *(const float4*)(A + (long)(m0+r)*K + (k0) + lkq*4)         \
                : make_float4(0.f,0.f,0.f,0.f);                               \
        }                                                                     \
        _Pragma("unroll")                                                     \
        for (int i = 0; i < NBLOAD; i++) {                                    \
            int r = lrow + i*64;                                              \
            regb[i] = (n0 + r < Nn)                                           \
                ? *(const float4*)(Bm + (long)(n0+r)*K + (k0) + lkq*4)        \
                : make_float4(0.f,0.f,0.f,0.f);                               \
        }                                                                     \
    }

#define STS_TILE(buf)                                                         \
    {                                                                         \
        _Pragma("unroll")                                                     \
        for (int i = 0; i < 2; i++) {                                         \
            int r = lrow + i*64;                                              \
            As[buf][lkq*4+0][r] = rega[i].x;                                  \
            As[buf][lkq*4+1][r] = rega[i].y;                                  \
            As[buf][lkq*4+2][r] = rega[i].z;                                  \
            As[buf][lkq*4+3][r] = rega[i].w;                                  \
        }                                                                     \
        _Pragma("unroll")                                                     \
        for (int i = 0; i < NBLOAD; i++) {                                    \
            int r = lrow + i*64;                                              \
            Bs[buf][lkq*4+0][r] = regb[i].x;                                  \
            Bs[buf][lkq*4+1][r] = regb[i].y;                                  \
            Bs[buf][lkq*4+2][r] = regb[i].z;                                  \
            Bs[buf][lkq*4+3][r] = regb[i].w;                                  \
        }                                                                     \
    }

#define COMPUTE_TILE(buf)                                                     \
    {                                                                         \
        _Pragma("unroll")                                                     \
        for (int kk = 0; kk < DBK_; kk++) {                                   \
            float a[8];                                                       \
            *(float4*)&a[0] = *(const float4*)&As[buf][kk][tm*8];             \
            *(float4*)&a[4] = *(const float4*)&As[buf][kk][tm*8+4];           \
            unsigned long long b2[TN/2];                                      \
            _Pragma("unroll")                                                 \
            for (int j = 0; j < TN/4; j++) {                                  \
                ulonglong2 t2 = *(const ulonglong2*)&Bs[buf][kk][tn*TN + j*4];\
                b2[j*2+0] = t2.x; b2[j*2+1] = t2.y;                           \
            }                                                                 \
            _Pragma("unroll")                                                 \
            for (int i = 0; i < 8; i++) {                                     \
                unsigned long long ra;                                        \
                PACK_DUP_F32(ra, a[i]);                                       \
                _Pragma("unroll")                                             \
                for (int j = 0; j < TN/2; j++)                                \
                    FMA_F32X2(acc[i][j], ra, b2[j], acc[i][j]);               \
            }                                                                 \
        }                                                                     \
    }

    // ---- pipelined main loop ----
    LDG_TILE(0);
    STS_TILE(0);
    __syncthreads();
    int buf = 0;
    for (int k0 = DBK_; k0 < K; k0 += DBK_) {
        LDG_TILE(k0);
        COMPUTE_TILE(buf);
        STS_TILE(buf ^ 1);
        __syncthreads();
        buf ^= 1;
    }
    COMPUTE_TILE(buf);

    // ---- epilogue ----
#pragma unroll
    for (int i = 0; i < 8; i++) {
        int row = m0 + tm*8 + i;
        if (row < M) {
#pragma unroll
            for (int j = 0; j < TN/2; j++) {
                int col = n0 + tn*TN + j*2;
                if (col < Nn) {
                    float2 v = *(float2*)&acc[i][j];
                    *(float2*)(C + (long)row*ldc + col) = v;
                }
            }
        }
    }
#undef LDG_TILE
#undef STS_TILE
#undef COMPUTE_TILE
}

// ---------------- small-N SGEMM (x_proj, Nn=44): C = A * B^T ----------------
#define BM_ 128
#define BN_ 64
#define BK_ 16
__global__ __launch_bounds__(128)
void sgemm(const float* __restrict__ A, const float* __restrict__ B,
           float* __restrict__ C, int M, int Nn, int K, int ldc)
{
    __shared__ float As[BK_][BM_];
    __shared__ float Bs[BK_][BN_];
    int tid = threadIdx.x;
    int tn = tid & 7;
    int tm = tid >> 3;
    int m0 = blockIdx.y * BM_;
    int n0 = blockIdx.x * BN_;
    float acc[8][8];
#pragma unroll
    for (int i = 0; i < 8; i++)
#pragma unroll
        for (int j = 0; j < 8; j++) acc[i][j] = 0.f;

    for (int k0 = 0; k0 < K; k0 += BK_) {
#pragma unroll
        for (int j = 0; j < 4; j++) {
            int idx = tid + j*128;
            int row = idx >> 2, kq = idx & 3;
            float4 v = make_float4(0.f,0.f,0.f,0.f);
            if (m0 + row < M) v = *(const float4*)(A + (long)(m0+row)*K + k0 + kq*4);
            As[kq*4+0][row] = v.x; As[kq*4+1][row] = v.y;
            As[kq*4+2][row] = v.z; As[kq*4+3][row] = v.w;
        }
#pragma unroll
        for (int j = 0; j < 2; j++) {
            int idx = tid + j*128;
            int row = idx >> 2, kq = idx & 3;
            float4 v = make_float4(0.f,0.f,0.f,0.f);
            if (n0 + row < Nn) v = *(const float4*)(B + (long)(n0+row)*K + k0 + kq*4);
            Bs[kq*4+0][row] = v.x; Bs[kq*4+1][row] = v.y;
            Bs[kq*4+2][row] = v.z; Bs[kq*4+3][row] = v.w;
        }
        __syncthreads();
#pragma unroll
        for (int kk = 0; kk < BK_; kk++) {
            float4 a0 = *(const float4*)&As[kk][tm*8];
            float4 a1 = *(const float4*)&As[kk][tm*8+4];
            float4 b0 = *(const float4*)&Bs[kk][tn*8];
            float4 b1 = *(const float4*)&Bs[kk][tn*8+4];
            float ra[8] = {a0.x,a0.y,a0.z,a0.w,a1.x,a1.y,a1.z,a1.w};
            float rb[8] = {b0.x,b0.y,b0.z,b0.w,b1.x,b1.y,b1.z,b1.w};
#pragma unroll
            for (int i = 0; i < 8; i++)
#pragma unroll
                for (int j = 0; j < 8; j++)
                    acc[i][j] = fmaf(ra[i], rb[j], acc[i][j]);
        }
        __syncthreads();
    }
#pragma unroll
    for (int i = 0; i < 8; i++) {
        int row = m0 + tm*8 + i;
        if (row < M) {
#pragma unroll
            for (int j = 0; j < 8; j++) {
                int col = n0 + tn*8 + j;
                if (col < Nn) C[(long)row*ldc + col] = acc[i][j];
            }
        }
    }
}

// ---------------- causal depthwise conv(4) + silu ----------------
__global__ void k_conv(const float* __restrict__ cw, const float* __restrict__ cb)
{
    int idx = blockIdx.x*blockDim.x + threadIdx.x;
    if (idx >= NTOK_*DI_) return;
    int d = idx % DI_;
    int t = idx / DI_;
    int l = t % L_;
    float acc = cb[d];
    const float* w = cw + d*4;
#pragma unroll
    for (int k = 0; k < 4; k++) {
        int ls = l - 3 + k;
        if (ls >= 0) acc = fmaf(g_xz[(long)(t + ls - l)*(2*DI_) + d], w[k], acc);
    }
    float sg = 1.f / (1.f + expf(-acc));
    g_xc[t*DI_ + d] = acc * sg;
}

// ---------------- dt = softplus(xdb[:, :12] @ dtw^T + dtb) ----------------
__global__ void k_dt(const float* __restrict__ dtw, const float* __restrict__ dtb)
{
    int idx = blockIdx.x*blockDim.x + threadIdx.x;
    if (idx >= NTOK_*DI_) return;
    int d = idx % DI_;
    int t = idx / DI_;
    float acc = dtb[d];
    const float* w = dtw + d*NR_;
    const float* x = g_xdb + (long)t*XP_;
#pragma unroll
    for (int r = 0; r < NR_; r++) acc = fmaf(x[r], w[r], acc);
    float sp = fmaxf(acc, 0.f) + log1pf(expf(-fabsf(acc)));
    g_dt[t*DI_ + d] = sp;
}

// ---------------- selective scan (serial over L, parallel over b,d) ----------------
__global__ __launch_bounds__(96)
void k_scan(const float* __restrict__ A_log, const float* __restrict__ Dsk)
{
    int d = blockIdx.x * 96 + threadIdx.x;   // 0..383
    int b = blockIdx.y;
    float a[NS_];
#pragma unroll
    for (int n = 0; n < NS_; n++) a[n] = -expf(A_log[d*NS_ + n]);
    float dsk = Dsk[d];
    float h[NS_];
#pragma unroll
    for (int n = 0; n < NS_; n++) h[n] = 0.f;

    for (int l = 0; l < L_; l++) {
        int t = b*L_ + l;
        const float4* q = (const float4*)(g_xdb + (long)t*XP_);
        float4 B0 = q[3], B1 = q[4], B2 = q[5], B3 = q[6];
        float4 C0 = q[7], C1 = q[8], C2 = q[9], C3 = q[10];
        float Bv[NS_] = {B0.x,B0.y,B0.z,B0.w, B1.x,B1.y,B1.z,B1.w,
                         B2.x,B2.y,B2.z,B2.w, B3.x,B3.y,B3.z,B3.w};
        float Cv[NS_] = {C0.x,C0.y,C0.z,C0.w, C1.x,C1.y,C1.z,C1.w,
                         C2.x,C2.y,C2.z,C2.w, C3.x,C3.y,C3.z,C3.w};
        float dt = g_dt[(long)t*DI_ + d];
        float u  = g_xc[(long)t*DI_ + d];
        float du = dt * u;
        float yv = 0.f;
#pragma unroll
        for (int n = 0; n < NS_; n++) {
            float dA = expf(dt * a[n]);
            h[n] = fmaf(h[n], dA, du * Bv[n]);
            yv = fmaf(h[n], Cv[n], yv);
        }
        float z = g_xz[(long)t*(2*DI_) + DI_ + d];
        float sg = z / (1.f + expf(-z));
        g_y[(long)t*DI_ + d] = (yv + u*dsk) * sg;
    }
}

// ---------------- layer-3 out_proj: only last tokens matter ----------------
__global__ void k_outlast(const float* __restrict__ ow)
{
    int b = blockIdx.x;
    int e = threadIdx.x;         // 192
    __shared__ float ys[DI_];
    int t = b*L_ + (L_-1);
    for (int i = e; i < DI_; i += E_) ys[i] = g_y[(long)t*DI_ + i];
    __syncthreads();
    float acc = 0.f;
    const float* w = ow + e*DI_;
#pragma unroll 4
    for (int d2 = 0; d2 < DI_; d2++) acc = fmaf(ys[d2], w[d2], acc);
    g_x[t*E_ + e] = acc;
}

// ---------------- final rmsnorm (last token) + classifier head ----------------
__global__ void k_final(const float* __restrict__ nfw, const float* __restrict__ hw,
                        const float* __restrict__ hb, float* __restrict__ out)
{
    int b = blockIdx.x;
    int e = threadIdx.x;         // 192
    int t = b*L_ + (L_-1);
    float r = g_x[t*E_ + e] + g_res[t*E_ + e];
    float s = r*r;
#pragma unroll
    for (int o = 16; o > 0; o >>= 1) s += __shfl_down_sync(0xffffffffu, s, o);
    __shared__ float ws[6];
    __shared__ float s_inv;
    __shared__ float vs[E_];
    int w = e >> 5, lane = e & 31;
    if (lane == 0) ws[w] = s;
    __syncthreads();
    if (e == 0) {
        float tot = ws[0]+ws[1]+ws[2]+ws[3]+ws[4]+ws[5];
        s_inv = rsqrtf(tot * (1.0f/E_) + EPS_);
    }
    __syncthreads();
    vs[e] = r * s_inv * nfw[e];
    __syncthreads();
    if (e < 20) {
        float acc = hb[e];
        const float* wr = hw + e*E_;
#pragma unroll 4
        for (int j = 0; j < E_; j++) acc = fmaf(vs[j], wr[j], acc);
        out[b*20 + e] = acc;
    }
}

// ---------------- launch ----------------
extern "C" void kernel_launch(void* const* d_in, const int* in_sizes, int n_in,
                              void* d_out, int out_size)
{
    const float* imgs      = (const float*)d_in[0];
    const float* patch_w   = (const float*)d_in[1];
    const float* patch_b   = (const float*)d_in[2];
    const float* cls_token = (const float*)d_in[3];
    const float* pos_embed = (const float*)d_in[4];
    const float* cnn_w     = (const float*)d_in[5];
    const float* cnn_b     = (const float*)d_in[6];
    const float* norm_w    = (const float*)d_in[7];
    const float* in_proj_w = (const float*)d_in[8];
    const float* conv_w    = (const float*)d_in[9];
    const float* conv_b    = (const float*)d_in[10];
    const float* x_proj_w  = (const float*)d_in[11];
    const float* dt_proj_w = (const float*)d_in[12];
    const float* dt_proj_b = (const float*)d_in[13];
    const float* A_log     = (const float*)d_in[14];
    const float* D_skip    = (const float*)d_in[15];
    const float* out_proj_w= (const float*)d_in[16];
    const float* norm_f_w  = (const float*)d_in[17];
    const float* head_w    = (const float*)d_in[18];
    const float* head_b    = (const float*)d_in[19];
    float* out = (float*)d_out;

    float *p_hn, *p_xz, *p_xc, *p_xdb, *p_y, *p_x;
    cudaGetSymbolAddress((void**)&p_hn,  g_hn);
    cudaGetSymbolAddress((void**)&p_xz,  g_xz);
    cudaGetSymbolAddress((void**)&p_xc,  g_xc);
    cudaGetSymbolAddress((void**)&p_xdb, g_xdb);
    cudaGetSymbolAddress((void**)&p_y,   g_y);
    cudaGetSymbolAddress((void**)&p_x,   g_x);

    k_embed<<<(NTOK_*E_ + 255)/256, 256>>>(imgs, patch_w, patch_b, cls_token,
                                           pos_embed, cnn_w, cnn_b);

    const int MGRID = (NTOK_ + 127) / 128;   // 101
    dim3 gIn (2*DI_/128, MGRID);   // (6,101)  TN=8
    dim3 gXp (1,         MGRID);   // (1,101)  small kernel
    dim3 gOut(E_/64,     MGRID);   // (3,101)  TN=4
    int ew_blocks = (NTOK_*DI_ + 255)/256;

    for (int i = 0; i < 4; i++) {
        k_resnorm<<<NTOK_, E_>>>(norm_w + i*E_, i == 0);
        sgemm_db<8><<<gIn, 256>>>(p_hn, in_proj_w + (long)i*2*DI_*E_, p_xz,
                                  NTOK_, 2*DI_, E_, 2*DI_);
        k_conv<<<ew_blocks, 256>>>(conv_w + (long)i*DI_*4, conv_b + i*DI_);
        sgemm<<<gXp, 128>>>(p_xc, x_proj_w + (long)i*(NR_+2*NS_)*DI_, p_xdb,
                            NTOK_, NR_+2*NS_, DI_, XP_);
        k_dt<<<ew_blocks, 256>>>(dt_proj_w + (long)i*DI_*NR_, dt_proj_b + i*DI_);
        k_scan<<<dim3(4, BATCH_), 96>>>(A_log + (long)i*DI_*NS_, D_skip + i*DI_);
        if (i < 3) {
            sgemm_db<4><<<gOut, 256>>>(p_y, out_proj_w + (long)i*E_*DI_, p_x,
                                       NTOK_, E_, DI_, E_);
        } else {
            k_outlast<<<BATCH_, E_>>>(out_proj_w + (long)i*E_*DI_);
        }
    }
    k_final<<<BATCH_, E_>>>(norm_f_w, head_w, head_b, out);
}

// round 4
// speedup vs baseline: 1.1478x; 1.1012x over previous
#include <cuda_runtime.h>

// ---------------- constants ----------------
#define E_    192
#define DI_   384
#define NS_   16
#define NR_   12
#define L_    401
#define BATCH_ 32
#define NTOK_ (BATCH_*L_)     // 12832
#define XP_   48              // padded xdb row stride (44 used)
#define EPS_  1e-5f

// ---------------- scratch (static device globals; no allocation) ----------------
__device__ float g_x  [NTOK_*E_];        // hidden
__device__ float g_res[NTOK_*E_];        // residual
__device__ float g_hn [NTOK_*E_];        // rmsnorm output
__device__ float g_xz [NTOK_*2*DI_];     // in_proj out (xm | z)
__device__ float g_xc [NTOK_*DI_];       // conv+silu out
__device__ float g_xdb[NTOK_*XP_];       // x_proj out (dt_r | B | C), padded
__device__ float g_y  [NTOK_*DI_];       // scan output (gated)

// ---------------- packed f32x2 helpers (sm_103a FFMA2) ----------------
#define FMA_F32X2(d, a, b, c) \
    asm("fma.rn.f32x2 %0, %1, %2, %3;" : "=l"(d) : "l"(a), "l"(b), "l"(c))
#define PACK_DUP_F32(d, x) \
    asm("mov.b64 %0, {%1, %1};" : "=l"(d) : "f"(x))

// ---------------- patch embed + pos + cnn conv + cls ----------------
__global__ void k_embed(const float* __restrict__ imgs, const float* __restrict__ pw,
                        const float* __restrict__ pb,   const float* __restrict__ cls,
                        const float* __restrict__ pos,  const float* __restrict__ cw,
                        const float* __restrict__ cb)
{
    int idx = blockIdx.x*blockDim.x + threadIdx.x;
    if (idx >= NTOK_*E_) return;
    int e = idx % E_;
    int t = idx / E_;
    int l = t % L_;
    int b = t / L_;
    float v;
    if (l == L_-1) {
        v = cls[e] + pos[(L_-1)*E_ + e];
    } else {
        float acc = cb[e];
        const float* w4 = pw + e*4;
#pragma unroll
        for (int k = 0; k < 3; k++) {
            int ls = l - 1 + k;
            if (ls >= 0 && ls < 400) {
                const float* im = imgs + b*1600 + ls*4;
                float pe = im[0]*w4[0] + im[1]*w4[1] + im[2]*w4[2] + im[3]*w4[3]
                         + pb[e] + pos[ls*E_ + e];
                acc = fmaf(pe, cw[e*3 + k], acc);
            }
        }
        v = acc;
    }
    g_x[t*E_ + e] = v;
}

// ---------------- residual accumulate + rmsnorm ----------------
__global__ void k_resnorm(const float* __restrict__ norm_w, int first)
{
    int t = blockIdx.x;
    int e = threadIdx.x;     // 192 threads
    float r = g_x[t*E_ + e];
    if (!first) r += g_res[t*E_ + e];
    g_res[t*E_ + e] = r;
    float s = r*r;
#pragma unroll
    for (int o = 16; o > 0; o >>= 1) s += __shfl_down_sync(0xffffffffu, s, o);
    __shared__ float ws[6];
    __shared__ float s_inv;
    int w = e >> 5, lane = e & 31;
    if (lane == 0) ws[w] = s;
    __syncthreads();
    if (e == 0) {
        float tot = ws[0]+ws[1]+ws[2]+ws[3]+ws[4]+ws[5];
        s_inv = rsqrtf(tot * (1.0f/E_) + EPS_);
    }
    __syncthreads();
    g_hn[t*E_ + e] = r * s_inv * norm_w[e];
}

// =========================================================================
// Double-buffered f32x2 SGEMM: C[M,Nn] = A[M,K] * B[Nn,K]^T
// 128 x (16*TN) tile, BK=16, 256 threads, 8 x TN microtile per thread.
// =========================================================================
#define DBK_ 16
template<int TN, int OCC>
__global__ __launch_bounds__(256, OCC)
void sgemm_db(const float* __restrict__ A, const float* __restrict__ Bm,
              float* __restrict__ C, int M, int Nn, int K, int ldc)
{
    constexpr int TBN = 16*TN;
    constexpr int NBLOAD = (TBN*DBK_/4)/256;   // float4 B loads per thread
    __shared__ float As[2][DBK_][128];
    __shared__ float Bs[2][DBK_][TBN];

    int tid = threadIdx.x;
    int tn = tid & 15;
    int tm = tid >> 4;
    int m0 = blockIdx.y * 128;
    int n0 = blockIdx.x * TBN;

    int lrow = tid >> 2;
    int lkq  = tid & 3;

    float4 rega[2];
    float4 regb[NBLOAD];

    unsigned long long acc[8][TN/2];
#pragma unroll
    for (int i = 0; i < 8; i++)
#pragma unroll
        for (int j = 0; j < TN/2; j++) acc[i][j] = 0ull;

#define LDG_TILE(k0)                                                          \
    {                                                                         \
        _Pragma("unroll")                                                     \
        for (int i = 0; i < 2; i++) {                                         \
            int r = lrow + i*64;                                              \
            rega[i] = (m0 + r < M)                                            \
                ? *(const float4*)(A + (long)(m0+r)*K + (k0) + lkq*4)         \
                : make_float4(0.f,0.f,0.f,0.f);                               \
        }                                                                     \
        _Pragma("unroll")                                                     \
        for (int i = 0; i < NBLOAD; i++) {                                    \
            int r = lrow + i*64;                                              \
            regb[i] = (n0 + r < Nn)                                           \
                ? *(const float4*)(Bm + (long)(n0+r)*K + (k0) + lkq*4)        \
                : make_float4(0.f,0.f,0.f,0.f);                               \
        }                                                                     \
    }

#define STS_TILE(buf)                                                         \
    {                                                                         \
        _Pragma("unroll")                                                     \
        for (int i = 0; i < 2; i++) {                                         \
            int r = lrow + i*64;                                              \
            As[buf][lkq*4+0][r] = rega[i].x;                                  \
            As[buf][lkq*4+1][r] = rega[i].y;                                  \
            As[buf][lkq*4+2][r] = rega[i].z;                                  \
            As[buf][lkq*4+3][r] = rega[i].w;                                  \
        }                                                                     \
        _Pragma("unroll")                                                     \
        for (int i = 0; i < NBLOAD; i++) {                                    \
            int r = lrow + i*64;                                              \
            Bs[buf][lkq*4+0][r] = regb[i].x;                                  \
            Bs[buf][lkq*4+1][r] = regb[i].y;                                  \
            Bs[buf][lkq*4+2][r] = regb[i].z;                                  \
            Bs[buf][lkq*4+3][r] = regb[i].w;                                  \
        }                                                                     \
    }

#define COMPUTE_TILE(buf)                                                     \
    {                                                                         \
        _Pragma("unroll")                                                     \
        for (int kk = 0; kk < DBK_; kk++) {                                   \
            float a[8];                                                       \
            *(float4*)&a[0] = *(const float4*)&As[buf][kk][tm*8];             \
            *(float4*)&a[4] = *(const float4*)&As[buf][kk][tm*8+4];           \
            unsigned long long b2[TN/2];                                      \
            _Pragma("unroll")                                                 \
            for (int j = 0; j < TN/4; j++) {                                  \
                ulonglong2 t2 = *(const ulonglong2*)&Bs[buf][kk][tn*TN + j*4];\
                b2[j*2+0] = t2.x; b2[j*2+1] = t2.y;                           \
            }                                                                 \
            _Pragma("unroll")                                                 \
            for (int i = 0; i < 8; i++) {                                     \
                unsigned long long ra;                                        \
                PACK_DUP_F32(ra, a[i]);                                       \
                _Pragma("unroll")                                             \
                for (int j = 0; j < TN/2; j++)                                \
                    FMA_F32X2(acc[i][j], ra, b2[j], acc[i][j]);               \
            }                                                                 \
        }                                                                     \
    }

    LDG_TILE(0);
    STS_TILE(0);
    __syncthreads();
    int buf = 0;
    for (int k0 = DBK_; k0 < K; k0 += DBK_) {
        LDG_TILE(k0);
        COMPUTE_TILE(buf);
        STS_TILE(buf ^ 1);
        __syncthreads();
        buf ^= 1;
    }
    COMPUTE_TILE(buf);

#pragma unroll
    for (int i = 0; i < 8; i++) {
        int row = m0 + tm*8 + i;
        if (row < M) {
#pragma unroll
            for (int j = 0; j < TN/2; j++) {
                int col = n0 + tn*TN + j*2;
                if (col < Nn) {
                    float2 v = *(float2*)&acc[i][j];
                    *(float2*)(C + (long)row*ldc + col) = v;
                }
            }
        }
    }
#undef LDG_TILE
#undef STS_TILE
#undef COMPUTE_TILE
}

// =========================================================================
// x_proj SGEMM: C[M,48(44 used)] = A[M,384] * B[44,384]^T, double-buffered
// 64x48 tile, 256 threads, microtile 4x3
// =========================================================================
__global__ __launch_bounds__(256)
void sgemm_xp(const float* __restrict__ A, const float* __restrict__ Bm,
              float* __restrict__ C, int M)
{
    __shared__ float As[2][16][64];
    __shared__ float Bs[2][16][48];
    int tid = threadIdx.x;
    int m0 = blockIdx.x * 64;
    int tm = tid >> 4;          // 0..15 -> 4 rows each
    int tn = tid & 15;          // 0..15 -> 3 cols each
    int lrow = tid >> 2;        // 0..63
    int lkq  = tid & 3;         // 0..3

    float acc[4][3];
#pragma unroll
    for (int i = 0; i < 4; i++)
#pragma unroll
        for (int j = 0; j < 3; j++) acc[i][j] = 0.f;

    float4 ra, rb;
#define XLDG(k0)                                                              \
    {                                                                         \
        ra = (m0 + lrow < M)                                                  \
            ? *(const float4*)(A + (long)(m0+lrow)*DI_ + (k0) + lkq*4)        \
            : make_float4(0.f,0.f,0.f,0.f);                                   \
        rb = make_float4(0.f,0.f,0.f,0.f);                                    \
        if (tid < 192 && lrow < 44)                                           \
            rb = *(const float4*)(Bm + (long)lrow*DI_ + (k0) + lkq*4);        \
    }
#define XSTS(buf)                                                             \
    {                                                                         \
        As[buf][lkq*4+0][lrow] = ra.x; As[buf][lkq*4+1][lrow] = ra.y;         \
        As[buf][lkq*4+2][lrow] = ra.z; As[buf][lkq*4+3][lrow] = ra.w;         \
        if (tid < 192) {                                                      \
            Bs[buf][lkq*4+0][lrow] = rb.x; Bs[buf][lkq*4+1][lrow] = rb.y;     \
            Bs[buf][lkq*4+2][lrow] = rb.z; Bs[buf][lkq*4+3][lrow] = rb.w;     \
        }                                                                     \
    }
#define XCOMP(buf)                                                            \
    {                                                                         \
        _Pragma("unroll")                                                     \
        for (int kk = 0; kk < 16; kk++) {                                     \
            float a4[4];                                                      \
            *(float4*)a4 = *(const float4*)&As[buf][kk][tm*4];                \
            float b0 = Bs[buf][kk][tn*3+0];                                   \
            float b1 = Bs[buf][kk][tn*3+1];                                   \
            float b2 = Bs[buf][kk][tn*3+2];                                   \
            _Pragma("unroll")                                                 \
            for (int i = 0; i < 4; i++) {                                     \
                acc[i][0] = fmaf(a4[i], b0, acc[i][0]);                       \
                acc[i][1] = fmaf(a4[i], b1, acc[i][1]);                       \
                acc[i][2] = fmaf(a4[i], b2, acc[i][2]);                       \
            }                                                                 \
        }                                                                     \
    }

    XLDG(0); XSTS(0);
    __syncthreads();
    int buf = 0;
    for (int k0 = 16; k0 < DI_; k0 += 16) {
        XLDG(k0);
        XCOMP(buf);
        XSTS(buf ^ 1);
        __syncthreads();
        buf ^= 1;
    }
    XCOMP(buf);

#pragma unroll
    for (int i = 0; i < 4; i++) {
        int row = m0 + tm*4 + i;
        if (row < M) {
#pragma unroll
            for (int j = 0; j < 3; j++)
                C[(long)row*XP_ + tn*3 + j] = acc[i][j];
        }
    }
#undef XLDG
#undef XSTS
#undef XCOMP
}

// ---------------- causal depthwise conv(4) + silu ----------------
__global__ void k_conv(const float* __restrict__ cw, const float* __restrict__ cb)
{
    int idx = blockIdx.x*blockDim.x + threadIdx.x;
    if (idx >= NTOK_*DI_) return;
    int d = idx % DI_;
    int t = idx / DI_;
    int l = t % L_;
    float acc = cb[d];
    const float* w = cw + d*4;
#pragma unroll
    for (int k = 0; k < 4; k++) {
        int ls = l - 3 + k;
        if (ls >= 0) acc = fmaf(g_xz[(long)(t + ls - l)*(2*DI_) + d], w[k], acc);
    }
    float sg = 1.f / (1.f + __expf(-acc));
    g_xc[t*DI_ + d] = acc * sg;
}

// =========================================================================
// Fused selective scan: dt(softplus of dot-12) + SSM + D-skip + z-gate.
// 4 threads per (b,d) channel, each owns 4 of 16 states.
// grid (12, 32), block 128  -> 49152 threads, ~10 warps/SM.
// =========================================================================
__global__ __launch_bounds__(128)
void k_scan(const float* __restrict__ A_log, const float* __restrict__ Dsk,
            const float* __restrict__ dtw_g, const float* __restrict__ dtb_g)
{
    int local = blockIdx.x*128 + threadIdx.x;   // 0..1535
    int d = local >> 2;                          // 0..383
    int q = local & 3;                           // which quarter of states
    int b = blockIdx.y;

    float a[4];
#pragma unroll
    for (int n = 0; n < 4; n++) a[n] = -__expf(A_log[d*NS_ + q*4 + n]);
    float w[NR_];
#pragma unroll
    for (int r = 0; r < NR_; r++) w[r] = dtw_g[d*NR_ + r];
    float dtb = dtb_g[d];
    float dsk = Dsk[d];
    float h[4] = {0.f, 0.f, 0.f, 0.f};

    long tbase = (long)b * L_;
    for (int l = 0; l < L_; l++) {
        long t = tbase + l;
        const float4* xr = (const float4*)(g_xdb + t*XP_);
        float4 r0 = xr[0], r1 = xr[1], r2 = xr[2];   // dt_r[0..11]
        float4 Bq = xr[3 + q];
        float4 Cq = xr[7 + q];
        float u = g_xc[t*DI_ + d];
        float z = g_xz[t*(2*DI_) + DI_ + d];

        float acc = dtb;
        acc = fmaf(r0.x, w[0], acc); acc = fmaf(r0.y, w[1],  acc);
        acc = fmaf(r0.z, w[2], acc); acc = fmaf(r0.w, w[3],  acc);
        acc = fmaf(r1.x, w[4], acc); acc = fmaf(r1.y, w[5],  acc);
        acc = fmaf(r1.z, w[6], acc); acc = fmaf(r1.w, w[7],  acc);
        acc = fmaf(r2.x, w[8], acc); acc = fmaf(r2.y, w[9],  acc);
        acc = fmaf(r2.z, w[10],acc); acc = fmaf(r2.w, w[11], acc);
        float dt = fmaxf(acc, 0.f) + __logf(1.f + __expf(-fabsf(acc)));
        float du = dt * u;

        float Bv[4] = {Bq.x, Bq.y, Bq.z, Bq.w};
        float Cv[4] = {Cq.x, Cq.y, Cq.z, Cq.w};
        float y = 0.f;
#pragma unroll
        for (int n = 0; n < 4; n++) {
            float dA = __expf(dt * a[n]);
            h[n] = fmaf(h[n], dA, du * Bv[n]);
            y = fmaf(h[n], Cv[n], y);
        }
        y += __shfl_xor_sync(0xffffffffu, y, 1);
        y += __shfl_xor_sync(0xffffffffu, y, 2);
        if (q == 0) {
            float sg = z / (1.f + __expf(-z));
            g_y[t*DI_ + d] = (y + u*dsk) * sg;
        }
    }
}

// ---------------- layer-3 out_proj: only last tokens matter ----------------
__global__ void k_outlast(const float* __restrict__ ow)
{
    int b = blockIdx.x;
    int e = threadIdx.x;         // 192
    __shared__ float ys[DI_];
    int t = b*L_ + (L_-1);
    for (int i = e; i < DI_; i += E_) ys[i] = g_y[(long)t*DI_ + i];
    __syncthreads();
    float acc = 0.f;
    const float* w = ow + e*DI_;
#pragma unroll 4
    for (int d2 = 0; d2 < DI_; d2++) acc = fmaf(ys[d2], w[d2], acc);
    g_x[t*E_ + e] = acc;
}

// ---------------- final rmsnorm (last token) + classifier head ----------------
__global__ void k_final(const float* __restrict__ nfw, const float* __restrict__ hw,
                        const float* __restrict__ hb, float* __restrict__ out)
{
    int b = blockIdx.x;
    int e = threadIdx.x;         // 192
    int t = b*L_ + (L_-1);
    float r = g_x[t*E_ + e] + g_res[t*E_ + e];
    float s = r*r;
#pragma unroll
    for (int o = 16; o > 0; o >>= 1) s += __shfl_down_sync(0xffffffffu, s, o);
    __shared__ float ws[6];
    __shared__ float s_inv;
    __shared__ float vs[E_];
    int w = e >> 5, lane = e & 31;
    if (lane == 0) ws[w] = s;
    __syncthreads();
    if (e == 0) {
        float tot = ws[0]+ws[1]+ws[2]+ws[3]+ws[4]+ws[5];
        s_inv = rsqrtf(tot * (1.0f/E_) + EPS_);
    }
    __syncthreads();
    vs[e] = r * s_inv * nfw[e];
    __syncthreads();
    if (e < 20) {
        float acc = hb[e];
        const float* wr = hw + e*E_;
#pragma unroll 4
        for (int j = 0; j < E_; j++) acc = fmaf(vs[j], wr[j], acc);
        out[b*20 + e] = acc;
    }
}

// ---------------- launch ----------------
extern "C" void kernel_launch(void* const* d_in, const int* in_sizes, int n_in,
                              void* d_out, int out_size)
{
    const float* imgs      = (const float*)d_in[0];
    const float* patch_w   = (const float*)d_in[1];
    const float* patch_b   = (const float*)d_in[2];
    const float* cls_token = (const float*)d_in[3];
    const float* pos_embed = (const float*)d_in[4];
    const float* cnn_w     = (const float*)d_in[5];
    const float* cnn_b     = (const float*)d_in[6];
    const float* norm_w    = (const float*)d_in[7];
    const float* in_proj_w = (const float*)d_in[8];
    const float* conv_w    = (const float*)d_in[9];
    const float* conv_b    = (const float*)d_in[10];
    const float* x_proj_w  = (const float*)d_in[11];
    const float* dt_proj_w = (const float*)d_in[12];
    const float* dt_proj_b = (const float*)d_in[13];
    const float* A_log     = (const float*)d_in[14];
    const float* D_skip    = (const float*)d_in[15];
    const float* out_proj_w= (const float*)d_in[16];
    const float* norm_f_w  = (const float*)d_in[17];
    const float* head_w    = (const float*)d_in[18];
    const float* head_b    = (const float*)d_in[19];
    float* out = (float*)d_out;

    float *p_hn, *p_xz, *p_xc, *p_xdb, *p_y, *p_x;
    cudaGetSymbolAddress((void**)&p_hn,  g_hn);
    cudaGetSymbolAddress((void**)&p_xz,  g_xz);
    cudaGetSymbolAddress((void**)&p_xc,  g_xc);
    cudaGetSymbolAddress((void**)&p_xdb, g_xdb);
    cudaGetSymbolAddress((void**)&p_y,   g_y);
    cudaGetSymbolAddress((void**)&p_x,   g_x);

    k_embed<<<(NTOK_*E_ + 255)/256, 256>>>(imgs, patch_w, patch_b, cls_token,
                                           pos_embed, cnn_w, cnn_b);

    const int MGRID = (NTOK_ + 127) / 128;   // 101
    dim3 gIn (2*DI_/128, MGRID);   // (6,101)  TN=8
    dim3 gOut(E_/64,     MGRID);   // (3,101)  TN=4
    int ew_blocks = (NTOK_*DI_ + 255)/256;
    int xp_blocks = (NTOK_ + 63) / 64;       // 201

    for (int i = 0; i < 4; i++) {
        k_resnorm<<<NTOK_, E_>>>(norm_w + i*E_, i == 0);
        sgemm_db<8,2><<<gIn, 256>>>(p_hn, in_proj_w + (long)i*2*DI_*E_, p_xz,
                                    NTOK_, 2*DI_, E_, 2*DI_);
        k_conv<<<ew_blocks, 256>>>(conv_w + (long)i*DI_*4, conv_b + i*DI_);
        sgemm_xp<<<xp_blocks, 256>>>(p_xc, x_proj_w + (long)i*(NR_+2*NS_)*DI_,
                                     p_xdb, NTOK_);
        k_scan<<<dim3(12, BATCH_), 128>>>(A_log + (long)i*DI_*NS_, D_skip + i*DI_,
                                          dt_proj_w + (long)i*DI_*NR_,
                                          dt_proj_b + i*DI_);
        if (i < 3) {
            sgemm_db<4,3><<<gOut, 256>>>(p_y, out_proj_w + (long)i*E_*DI_, p_x,
                                         NTOK_, E_, DI_, E_);
        } else {
            k_outlast<<<BATCH_, E_>>>(out_proj_w + (long)i*E_*DI_);
        }
    }
    k_final<<<BATCH_, E_>>>(norm_f_w, head_w, head_b, out);
}

// round 6
// speedup vs baseline: 1.9677x; 1.7143x over previous
#include <cuda_runtime.h>
#include <cuda_bf16.h>
#include <cstdint>

// ---------------- constants ----------------
#define E_    192
#define DI_   384
#define NS_   16
#define NR_   12
#define L_    401
#define BATCH_ 32
#define NTOK_ (BATCH_*L_)     // 12832
#define XP_   48              // padded xdb row stride (44 used)
#define EPS_  1e-5f

// ---------------- scratch (static device globals; no allocation) ----------------
__device__ float g_x  [NTOK_*E_];        // hidden
__device__ float g_res[NTOK_*E_];        // residual
__device__ float g_hn [NTOK_*E_];        // rmsnorm output
__device__ float g_xz [NTOK_*2*DI_];     // in_proj out (xm | z)
__device__ float g_xc [NTOK_*DI_];       // conv+silu out
__device__ float g_xdb[NTOK_*XP_];       // x_proj out (dt_r | B | C), padded
__device__ float g_y  [NTOK_*DI_];       // scan output (gated)

// bf16 hi/lo packed operands for tensor-core GEMMs
__device__ __nv_bfloat16 g_a2 [(long)NTOK_*3*E_];    // in_proj A'  [M, 576]
__device__ __nv_bfloat16 g_b2 [(long)768*3*E_];      // in_proj B'  [768, 576]
__device__ __nv_bfloat16 g_a2o[(long)NTOK_*3*DI_];   // out_proj A' [M, 1152]
__device__ __nv_bfloat16 g_b2o[(long)E_*3*DI_];      // out_proj B' [192, 1152]

// ---------------- warp-MMA helpers (compute_103-safe PTX) ----------------
__device__ __forceinline__ uint32_t smem_u32(const void* p) {
    uint32_t a;
    asm("{ .reg .u64 t; cvta.to.shared.u64 t, %1; cvt.u32.u64 %0, t; }"
        : "=r"(a) : "l"(p));
    return a;
}
__device__ __forceinline__ void ldsm4(uint32_t* r, uint32_t addr) {
    asm volatile("ldmatrix.sync.aligned.m8n8.x4.shared.b16 {%0,%1,%2,%3}, [%4];"
        : "=r"(r[0]), "=r"(r[1]), "=r"(r[2]), "=r"(r[3]) : "r"(addr));
}
__device__ __forceinline__ void mma_bf16(float* c, const uint32_t* a, const uint32_t* b) {
    asm volatile("mma.sync.aligned.m16n8k16.row.col.f32.bf16.bf16.f32 "
        "{%0,%1,%2,%3}, {%4,%5,%6,%7}, {%8,%9}, {%0,%1,%2,%3};"
        : "+f"(c[0]), "+f"(c[1]), "+f"(c[2]), "+f"(c[3])
        : "r"(a[0]), "r"(a[1]), "r"(a[2]), "r"(a[3]), "r"(b[0]), "r"(b[1]));
}

// ---------------- patch embed + pos + cnn conv + cls ----------------
__global__ void k_embed(const float* __restrict__ imgs, const float* __restrict__ pw,
                        const float* __restrict__ pb,   const float* __restrict__ cls,
                        const float* __restrict__ pos,  const float* __restrict__ cw,
                        const float* __restrict__ cb)
{
    int idx = blockIdx.x*blockDim.x + threadIdx.x;
    if (idx >= NTOK_*E_) return;
    int e = idx % E_;
    int t = idx / E_;
    int l = t % L_;
    int b = t / L_;
    float v;
    if (l == L_-1) {
        v = cls[e] + pos[(L_-1)*E_ + e];
    } else {
        float acc = cb[e];
        const float* w4 = pw + e*4;
#pragma unroll
        for (int k = 0; k < 3; k++) {
            int ls = l - 1 + k;
            if (ls >= 0 && ls < 400) {
                const float* im = imgs + b*1600 + ls*4;
                float pe = im[0]*w4[0] + im[1]*w4[1] + im[2]*w4[2] + im[3]*w4[3]
                         + pb[e] + pos[ls*E_ + e];
                acc = fmaf(pe, cw[e*3 + k], acc);
            }
        }
        v = acc;
    }
    g_x[t*E_ + e] = v;
}

// ---------------- residual accumulate + rmsnorm ----------------
__global__ void k_resnorm(const float* __restrict__ norm_w, int first)
{
    int t = blockIdx.x;
    int e = threadIdx.x;     // 192 threads
    float r = g_x[t*E_ + e];
    if (!first) r += g_res[t*E_ + e];
    g_res[t*E_ + e] = r;
    float s = r*r;
#pragma unroll
    for (int o = 16; o > 0; o >>= 1) s += __shfl_down_sync(0xffffffffu, s, o);
    __shared__ float ws[6];
    __shared__ float s_inv;
    int w = e >> 5, lane = e & 31;
    if (lane == 0) ws[w] = s;
    __syncthreads();
    if (e == 0) {
        float tot = ws[0]+ws[1]+ws[2]+ws[3]+ws[4]+ws[5];
        s_inv = rsqrtf(tot * (1.0f/E_) + EPS_);
    }
    __syncthreads();
    g_hn[t*E_ + e] = r * s_inv * norm_w[e];
}

// ---------------- f32 -> bf16 hi/lo split, packed K-dim ----------------
// mode 0 (A side): [hi | lo | hi] ; mode 1 (B side): [hi | hi | lo]
__global__ void k_cvt(const float* __restrict__ src, __nv_bfloat16* __restrict__ dst,
                      int R, int K, int bmode)
{
    int idx = blockIdx.x*blockDim.x + threadIdx.x;
    if (idx >= R*K) return;
    int k = idx % K, r = idx / K;
    float x = src[idx];
    __nv_bfloat16 hi = __float2bfloat16(x);
    __nv_bfloat16 lo = __float2bfloat16(x - __bfloat162float(hi));
    long base = (long)r*3*K;
    dst[base + k] = hi;
    if (bmode) { dst[base + K + k] = hi; dst[base + 2*K + k] = lo; }
    else       { dst[base + K + k] = lo; dst[base + 2*K + k] = hi; }
}

// =========================================================================
// HMMA bf16 GEMM: C[M,Nn] = A2[M,Keff] * B2[Nn,Keff]^T (fp32 accum)
// CTA tile 128 x BN, BK=32, double-buffered smem, warp tile 64x32.
// =========================================================================
template<int BN, int NTH>
__global__ __launch_bounds__(NTH)
void hgemm(const __nv_bfloat16* __restrict__ A2, const __nv_bfloat16* __restrict__ B2,
           float* __restrict__ C, int M, int Keff, int Nn, int ldc)
{
    constexpr int WN = BN/32;                 // warps along N
    constexpr int NLA = 512/NTH;              // A uint4 loads per thread
    constexpr int NLB = (BN*4)/NTH;           // B uint4 loads per thread
    constexpr int ASTRIDE = 40;               // bf16 elems per smem row
    __shared__ __align__(16) __nv_bfloat16 sA[2][128][ASTRIDE];
    __shared__ __align__(16) __nv_bfloat16 sB[2][BN][ASTRIDE];
    constexpr uint32_t ABUF = 128*ASTRIDE*2;  // bytes per A buffer
    constexpr uint32_t BBUF = BN*ASTRIDE*2;

    int tid = threadIdx.x, wid = tid >> 5, lane = tid & 31;
    int wm = wid / WN, wn = wid % WN;
    int m0 = blockIdx.y * 128;
    int n0 = blockIdx.x * BN;

    // ldmatrix lane addresses (buffer 0, k-step 0)
    uint32_t a_addr[4], b_addr[2];
#pragma unroll
    for (int am = 0; am < 4; am++) {
        int row = wm*64 + am*16 + (lane & 15);
        int colb = (lane >> 4) * 16;
        a_addr[am] = smem_u32(&sA[0][row][0]) + colb;
    }
#pragma unroll
    for (int p = 0; p < 2; p++) {
        int row = wn*32 + p*16 + (lane & 7) + ((lane >> 4) << 3);
        int colb = ((lane >> 3) & 1) * 16;
        b_addr[p] = smem_u32(&sB[0][row][0]) + colb;
    }

    float c[4][4][4];
#pragma unroll
    for (int i = 0; i < 4; i++)
#pragma unroll
        for (int j = 0; j < 4; j++)
#pragma unroll
            for (int k = 0; k < 4; k++) c[i][j][k] = 0.f;

    uint4 ra[NLA], rb[NLB];

#define H_LDG(k0)                                                             \
    {                                                                         \
        _Pragma("unroll")                                                     \
        for (int i = 0; i < NLA; i++) {                                       \
            int g = tid + i*NTH;                                              \
            int row = g >> 2, seg = g & 3;                                    \
            ra[i] = (m0 + row < M)                                            \
                ? *(const uint4*)(A2 + (long)(m0+row)*Keff + (k0) + seg*8)    \
                : make_uint4(0u,0u,0u,0u);                                    \
        }                                                                     \
        _Pragma("unroll")                                                     \
        for (int i = 0; i < NLB; i++) {                                       \
            int g = tid + i*NTH;                                              \
            int row = g >> 2, seg = g & 3;                                    \
            rb[i] = *(const uint4*)(B2 + (long)(n0+row)*Keff + (k0) + seg*8); \
        }                                                                     \
    }
#define H_STS(buf)                                                            \
    {                                                                         \
        _Pragma("unroll")                                                     \
        for (int i = 0; i < NLA; i++) {                                       \
            int g = tid + i*NTH;                                              \
            int row = g >> 2, seg = g & 3;                                    \
            *(uint4*)&sA[buf][row][seg*8] = ra[i];                            \
        }                                                                     \
        _Pragma("unroll")                                                     \
        for (int i = 0; i < NLB; i++) {                                       \
            int g = tid + i*NTH;                                              \
            int row = g >> 2, seg = g & 3;                                    \
            *(uint4*)&sB[buf][row][seg*8] = rb[i];                            \
        }                                                                     \
    }
#define H_COMP(buf)                                                           \
    {                                                                         \
        uint32_t aoff = (buf)*ABUF, boff = (buf)*BBUF;                        \
        _Pragma("unroll")                                                     \
        for (int ks = 0; ks < 2; ks++) {                                      \
            uint32_t af[4][4], bf[2][4];                                      \
            _Pragma("unroll")                                                 \
            for (int am = 0; am < 4; am++)                                    \
                ldsm4(af[am], a_addr[am] + aoff + ks*32);                     \
            _Pragma("unroll")                                                 \
            for (int p = 0; p < 2; p++)                                       \
                ldsm4(bf[p], b_addr[p] + boff + ks*32);                       \
            _Pragma("unroll")                                                 \
            for (int am = 0; am < 4; am++)                                    \
                _Pragma("unroll")                                             \
                for (int bn = 0; bn < 4; bn++)                                \
                    mma_bf16(c[am][bn], af[am], &bf[bn>>1][(bn&1)*2]);        \
        }                                                                     \
    }

    int nchunk = Keff >> 5;
    H_LDG(0);
    H_STS(0);
    __syncthreads();
    for (int ck = 0; ck < nchunk; ck++) {
        if (ck + 1 < nchunk) H_LDG((ck+1)*32);
        H_COMP(ck & 1);
        if (ck + 1 < nchunk) {
            H_STS((ck+1) & 1);
        }
        __syncthreads();
    }

    // epilogue: direct fp32 stores
#pragma unroll
    for (int am = 0; am < 4; am++) {
        int r0 = m0 + wm*64 + am*16 + (lane >> 2);
        int r1 = r0 + 8;
#pragma unroll
        for (int bn = 0; bn < 4; bn++) {
            int col = n0 + wn*32 + bn*8 + (lane & 3)*2;
            if (r0 < M) *(float2*)(C + (long)r0*ldc + col) = make_float2(c[am][bn][0], c[am][bn][1]);
            if (r1 < M) *(float2*)(C + (long)r1*ldc + col) = make_float2(c[am][bn][2], c[am][bn][3]);
        }
    }
#undef H_LDG
#undef H_STS
#undef H_COMP
}

// =========================================================================
// x_proj SGEMM: C[M,48(44 used)] = A[M,384] * B[44,384]^T, double-buffered
// =========================================================================
__global__ __launch_bounds__(256)
void sgemm_xp(const float* __restrict__ A, const float* __restrict__ Bm,
              float* __restrict__ C, int M)
{
    __shared__ float As[2][16][64];
    __shared__ float Bs[2][16][48];
    int tid = threadIdx.x;
    int m0 = blockIdx.x * 64;
    int tm = tid >> 4;          // 0..15 -> 4 rows each
    int tn = tid & 15;          // 0..15 -> 3 cols each
    int lrow = tid >> 2;        // 0..63
    int lkq  = tid & 3;         // 0..3

    float acc[4][3];
#pragma unroll
    for (int i = 0; i < 4; i++)
#pragma unroll
        for (int j = 0; j < 3; j++) acc[i][j] = 0.f;

    float4 ra, rb;
#define XLDG(k0)                                                              \
    {                                                                         \
        ra = (m0 + lrow < M)                                                  \
            ? *(const float4*)(A + (long)(m0+lrow)*DI_ + (k0) + lkq*4)        \
            : make_float4(0.f,0.f,0.f,0.f);                                   \
        rb = make_float4(0.f,0.f,0.f,0.f);                                    \
        if (tid < 192 && lrow < 44)                                           \
            rb = *(const float4*)(Bm + (long)lrow*DI_ + (k0) + lkq*4);        \
    }
#define XSTS(buf)                                                             \
    {                                                                         \
        As[buf][lkq*4+0][lrow] = ra.x; As[buf][lkq*4+1][lrow] = ra.y;         \
        As[buf][lkq*4+2][lrow] = ra.z; As[buf][lkq*4+3][lrow] = ra.w;         \
        if (tid < 192) {                                                      \
            Bs[buf][lkq*4+0][lrow] = rb.x; Bs[buf][lkq*4+1][lrow] = rb.y;     \
            Bs[buf][lkq*4+2][lrow] = rb.z; Bs[buf][lkq*4+3][lrow] = rb.w;     \
        }                                                                     \
    }
#define XCOMP(buf)                                                            \
    {                                                                         \
        _Pragma("unroll")                                                     \
        for (int kk = 0; kk < 16; kk++) {                                     \
            float a4[4];                                                      \
            *(float4*)a4 = *(const float4*)&As[buf][kk][tm*4];                \
            float b0 = Bs[buf][kk][tn*3+0];                                   \
            float b1 = Bs[buf][kk][tn*3+1];                                   \
            float b2 = Bs[buf][kk][tn*3+2];                                   \
            _Pragma("unroll")                                                 \
            for (int i = 0; i < 4; i++) {                                     \
                acc[i][0] = fmaf(a4[i], b0, acc[i][0]);                       \
                acc[i][1] = fmaf(a4[i], b1, acc[i][1]);                       \
                acc[i][2] = fmaf(a4[i], b2, acc[i][2]);                       \
            }                                                                 \
        }                                                                     \
    }

    XLDG(0); XSTS(0);
    __syncthreads();
    int buf = 0;
    for (int k0 = 16; k0 < DI_; k0 += 16) {
        XLDG(k0);
        XCOMP(buf);
        XSTS(buf ^ 1);
        __syncthreads();
        buf ^= 1;
    }
    XCOMP(buf);

#pragma unroll
    for (int i = 0; i < 4; i++) {
        int row = m0 + tm*4 + i;
        if (row < M) {
#pragma unroll
            for (int j = 0; j < 3; j++)
                C[(long)row*XP_ + tn*3 + j] = acc[i][j];
        }
    }
#undef XLDG
#undef XSTS
#undef XCOMP
}

// ---------------- causal depthwise conv(4) + silu ----------------
__global__ void k_conv(const float* __restrict__ cw, const float* __restrict__ cb)
{
    int idx = blockIdx.x*blockDim.x + threadIdx.x;
    if (idx >= NTOK_*DI_) return;
    int d = idx % DI_;
    int t = idx / DI_;
    int l = t % L_;
    float acc = cb[d];
    const float* w = cw + d*4;
#pragma unroll
    for (int k = 0; k < 4; k++) {
        int ls = l - 3 + k;
        if (ls >= 0) acc = fmaf(g_xz[(long)(t + ls - l)*(2*DI_) + d], w[k], acc);
    }
    float sg = 1.f / (1.f + __expf(-acc));
    g_xc[t*DI_ + d] = acc * sg;
}

// =========================================================================
// Fused selective scan with software-pipelined loads.
// 4 threads per (b,d) channel, each owns 4 of 16 states.
// grid (12, 32), block 128.
// =========================================================================
__global__ __launch_bounds__(128)
void k_scan(const float* __restrict__ A_log, const float* __restrict__ Dsk,
            const float* __restrict__ dtw_g, const float* __restrict__ dtb_g)
{
    int local = blockIdx.x*128 + threadIdx.x;   // 0..1535
    int d = local >> 2;                          // 0..383
    int q = local & 3;                           // quarter of states
    int b = blockIdx.y;

    float a[4];
#pragma unroll
    for (int n = 0; n < 4; n++) a[n] = -__expf(A_log[d*NS_ + q*4 + n]);
    float w[NR_];
#pragma unroll
    for (int r = 0; r < NR_; r++) w[r] = dtw_g[d*NR_ + r];
    float dtb = dtb_g[d];
    float dsk = Dsk[d];
    float h[4] = {0.f, 0.f, 0.f, 0.f};

    long tbase = (long)b * L_;
    const float4* xr = (const float4*)(g_xdb + tbase*XP_);
    float4 r0 = xr[0], r1 = xr[1], r2 = xr[2];
    float4 Bq = xr[3+q], Cq = xr[7+q];
    float u = g_xc[tbase*DI_ + d];
    float z = g_xz[tbase*(2*DI_) + DI_ + d];

    for (int l = 0; l < L_; l++) {
        long t = tbase + l;
        long t2 = tbase + ((l+1 < L_) ? l+1 : l);
        const float4* x2 = (const float4*)(g_xdb + t2*XP_);
        float4 p0 = x2[0], p1 = x2[1], p2 = x2[2];
        float4 pB = x2[3+q], pC = x2[7+q];
        float pu = g_xc[t2*DI_ + d];
        float pz = g_xz[t2*(2*DI_) + DI_ + d];

        float a0 = dtb, a1 = 0.f;
        a0 = fmaf(r0.x, w[0], a0); a1 = fmaf(r0.y, w[1],  a1);
        a0 = fmaf(r0.z, w[2], a0); a1 = fmaf(r0.w, w[3],  a1);
        a0 = fmaf(r1.x, w[4], a0); a1 = fmaf(r1.y, w[5],  a1);
        a0 = fmaf(r1.z, w[6], a0); a1 = fmaf(r1.w, w[7],  a1);
        a0 = fmaf(r2.x, w[8], a0); a1 = fmaf(r2.y, w[9],  a1);
        a0 = fmaf(r2.z, w[10],a0); a1 = fmaf(r2.w, w[11], a1);
        float acc = a0 + a1;
        float dt = fmaxf(acc, 0.f) + __logf(1.f + __expf(-fabsf(acc)));
        float du = dt * u;

        float Bv[4] = {Bq.x, Bq.y, Bq.z, Bq.w};
        float Cv[4] = {Cq.x, Cq.y, Cq.z, Cq.w};
        float y = 0.f;
#pragma unroll
        for (int n = 0; n < 4; n++) {
            float dA = __expf(dt * a[n]);
            h[n] = fmaf(h[n], dA, du * Bv[n]);
            y = fmaf(h[n], Cv[n], y);
        }
        y += __shfl_xor_sync(0xffffffffu, y, 1);
        y += __shfl_xor_sync(0xffffffffu, y, 2);
        if (q == 0) {
            float sg = z / (1.f + __expf(-z));
            g_y[t*DI_ + d] = (y + u*dsk) * sg;
        }
        r0 = p0; r1 = p1; r2 = p2; Bq = pB; Cq = pC; u = pu; z = pz;
    }
}

// ---------------- layer-3 out_proj: only last tokens matter ----------------
__global__ void k_outlast(const float* __restrict__ ow)
{
    int b = blockIdx.x;
    int e = threadIdx.x;         // 192
    __shared__ float ys[DI_];
    int t = b*L_ + (L_-1);
    for (int i = e; i < DI_; i += E_) ys[i] = g_y[(long)t*DI_ + i];
    __syncthreads();
    float acc = 0.f;
    const float* w = ow + e*DI_;
#pragma unroll 4
    for (int d2 = 0; d2 < DI_; d2++) acc = fmaf(ys[d2], w[d2], acc);
    g_x[t*E_ + e] = acc;
}

// ---------------- final rmsnorm (last token) + classifier head ----------------
__global__ void k_final(const float* __restrict__ nfw, const float* __restrict__ hw,
                        const float* __restrict__ hb, float* __restrict__ out)
{
    int b = blockIdx.x;
    int e = threadIdx.x;         // 192
    int t = b*L_ + (L_-1);
    float r = g_x[t*E_ + e] + g_res[t*E_ + e];
    float s = r*r;
#pragma unroll
    for (int o = 16; o > 0; o >>= 1) s += __shfl_down_sync(0xffffffffu, s, o);
    __shared__ float ws[6];
    __shared__ float s_inv;
    __shared__ float vs[E_];
    int w = e >> 5, lane = e & 31;
    if (lane == 0) ws[w] = s;
    __syncthreads();
    if (e == 0) {
        float tot = ws[0]+ws[1]+ws[2]+ws[3]+ws[4]+ws[5];
        s_inv = rsqrtf(tot * (1.0f/E_) + EPS_);
    }
    __syncthreads();
    vs[e] = r * s_inv * nfw[e];
    __syncthreads();
    if (e < 20) {
        float acc = hb[e];
        const float* wr = hw + e*E_;
#pragma unroll 4
        for (int j = 0; j < E_; j++) acc = fmaf(vs[j], wr[j], acc);
        out[b*20 + e] = acc;
    }
}

// ---------------- launch ----------------
extern "C" void kernel_launch(void* const* d_in, const int* in_sizes, int n_in,
                              void* d_out, int out_size)
{
    const float* imgs      = (const float*)d_in[0];
    const float* patch_w   = (const float*)d_in[1];
    const float* patch_b   = (const float*)d_in[2];
    const float* cls_token = (const float*)d_in[3];
    const float* pos_embed = (const float*)d_in[4];
    const float* cnn_w     = (const float*)d_in[5];
    const float* cnn_b     = (const float*)d_in[6];
    const float* norm_w    = (const float*)d_in[7];
    const float* in_proj_w = (const float*)d_in[8];
    const float* conv_w    = (const float*)d_in[9];
    const float* conv_b    = (const float*)d_in[10];
    const float* x_proj_w  = (const float*)d_in[11];
    const float* dt_proj_w = (const float*)d_in[12];
    const float* dt_proj_b = (const float*)d_in[13];
    const float* A_log     = (const float*)d_in[14];
    const float* D_skip    = (const float*)d_in[15];
    const float* out_proj_w= (const float*)d_in[16];
    const float* norm_f_w  = (const float*)d_in[17];
    const float* head_w    = (const float*)d_in[18];
    const float* head_b    = (const float*)d_in[19];
    float* out = (float*)d_out;

    float *p_hn, *p_xz, *p_xc, *p_xdb, *p_y, *p_x;
    __nv_bfloat16 *p_a2, *p_b2, *p_a2o, *p_b2o;
    cudaGetSymbolAddress((void**)&p_hn,  g_hn);
    cudaGetSymbolAddress((void**)&p_xz,  g_xz);
    cudaGetSymbolAddress((void**)&p_xc,  g_xc);
    cudaGetSymbolAddress((void**)&p_xdb, g_xdb);
    cudaGetSymbolAddress((void**)&p_y,   g_y);
    cudaGetSymbolAddress((void**)&p_x,   g_x);
    cudaGetSymbolAddress((void**)&p_a2,  g_a2);
    cudaGetSymbolAddress((void**)&p_b2,  g_b2);
    cudaGetSymbolAddress((void**)&p_a2o, g_a2o);
    cudaGetSymbolAddress((void**)&p_b2o, g_b2o);

    k_embed<<<(NTOK_*E_ + 255)/256, 256>>>(imgs, patch_w, patch_b, cls_token,
                                           pos_embed, cnn_w, cnn_b);

    const int MGRID = (NTOK_ + 127) / 128;   // 101
    dim3 gIn (6, MGRID);    // N tiles of 128 over 768
    dim3 gOut(3, MGRID);    // N tiles of 64 over 192
    int ew_blocks = (NTOK_*DI_ + 255)/256;
    int xp_blocks = (NTOK_ + 63) / 64;       // 201
    int cvtA_in  = (NTOK_*E_  + 255)/256;
    int cvtA_out = (NTOK_*DI_ + 255)/256;
    int cvtB_in  = (768*E_  + 255)/256;
    int cvtB_out = (E_*DI_  + 255)/256;

    for (int i = 0; i < 4; i++) {
        k_resnorm<<<NTOK_, E_>>>(norm_w + i*E_, i == 0);
        k_cvt<<<cvtA_in, 256>>>(p_hn, p_a2, NTOK_, E_, 0);
        k_cvt<<<cvtB_in, 256>>>(in_proj_w + (long)i*2*DI_*E_, p_b2, 2*DI_, E_, 1);
        hgemm<128,256><<<gIn, 256>>>(p_a2, p_b2, p_xz, NTOK_, 3*E_, 2*DI_, 2*DI_);
        k_conv<<<ew_blocks, 256>>>(conv_w + (long)i*DI_*4, conv_b + i*DI_);
        sgemm_xp<<<xp_blocks, 256>>>(p_xc, x_proj_w + (long)i*(NR_+2*NS_)*DI_,
                                     p_xdb, NTOK_);
        k_scan<<<dim3(12, BATCH_), 128>>>(A_log + (long)i*DI_*NS_, D_skip + i*DI_,
                                          dt_proj_w + (long)i*DI_*NR_,
                                          dt_proj_b + i*DI_);
        if (i < 3) {
            k_cvt<<<cvtA_out, 256>>>(p_y, p_a2o, NTOK_, DI_, 0);
            k_cvt<<<cvtB_out, 256>>>(out_proj_w + (long)i*E_*DI_, p_b2o, E_, DI_, 1);
            hgemm<64,128><<<gOut, 128>>>(p_a2o, p_b2o, p_x, NTOK_, 3*DI_, E_, E_);
        } else {
            k_outlast<<<BATCH_, E_>>>(out_proj_w + (long)i*E_*DI_);
        }
    }
    k_final<<<BATCH_, E_>>>(norm_f_w, head_w, head_b, out);
}